// round 10
// baseline (speedup 1.0000x reference)
#include <cuda_runtime.h>
#include <cstdint>

#define NN   100000
#define NE   800000
#define F0   128
#define C1   256
#define C2   128
#define NOUT 6

// ---------------- scratch (device globals: allocation-free rule) ------------
__device__ float g_xw [(size_t)NN * C1];
__device__ float g_agg[(size_t)NN * C1];
__device__ float g_as [NN];
__device__ float g_ad [NN];
__device__ int   g_deg[NN];
__device__ int   g_rowptr[NN];
__device__ int   g_cur[NN];
__device__ int   g_bsum[256];
__device__ int   g_csr[NN + NE];

// ---------------- tf32 helpers ----------------------------------------------
__device__ __forceinline__ uint32_t f2tf32(float f) {
    uint32_t u;
    asm("cvt.rna.tf32.f32 %0, %1;" : "=r"(u) : "f"(f));
    return u;
}
__device__ __forceinline__ void mma_tf32(float* c, const uint32_t* a, const uint32_t* b) {
    asm volatile(
        "mma.sync.aligned.m16n8k8.row.col.f32.tf32.tf32.f32 "
        "{%0,%1,%2,%3}, {%4,%5,%6,%7}, {%8,%9}, {%0,%1,%2,%3};"
        : "+f"(c[0]), "+f"(c[1]), "+f"(c[2]), "+f"(c[3])
        : "r"(a[0]), "r"(a[1]), "r"(a[2]), "r"(a[3]), "r"(b[0]), "r"(b[1]));
}

#define SA_LD 36
#define SB_LD 136

// ============================================================================
// GEMM1 (mma.sync tf32): xw = x @ W  [M,128]x[128,256] + fused alpha partials
// ============================================================================
__global__ void __launch_bounds__(256, 2)
gat_gemm1(const float* __restrict__ X, const float* __restrict__ W,
          const float* __restrict__ a_srcp, const float* __restrict__ a_dstp,
          float* __restrict__ XW, int M)
{
    __shared__ uint32_t sA[128 * SA_LD];
    __shared__ uint32_t sB[32 * SB_LD];
    __shared__ float sAs[128], sAd[128];

    const int tid   = threadIdx.x;
    const int lane  = tid & 31;
    const int wid   = tid >> 5;
    const int qid   = lane >> 2;
    const int tq    = lane & 3;
    const int warpM = wid & 1;
    const int warpN = wid >> 1;
    const int bm0   = blockIdx.y * 128;
    const int bn0   = blockIdx.x * 128;

    if (tid < 128) { sAs[tid] = a_srcp[bn0 + tid]; sAd[tid] = a_dstp[bn0 + tid]; }

    float acc[4][4][4];
#pragma unroll
    for (int i = 0; i < 4; i++)
#pragma unroll
        for (int j = 0; j < 4; j++)
#pragma unroll
            for (int q = 0; q < 4; q++) acc[i][j][q] = 0.f;

    const int arow = tid >> 1, acol = (tid & 1) * 16;
    const int brow = tid >> 3, bcol = (tid & 7) * 16;

    for (int kt = 0; kt < F0 / 32; kt++) {
        {
            bool valid = (bm0 + arow) < M;
            const float* gp = X + (size_t)(bm0 + arow) * F0 + kt * 32 + acol;
#pragma unroll
            for (int q = 0; q < 4; q++) {
                float4 v = valid ? *(const float4*)(gp + q * 4)
                                 : make_float4(0.f, 0.f, 0.f, 0.f);
                uint32_t* s = &sA[arow * SA_LD + acol + q * 4];
                s[0] = f2tf32(v.x); s[1] = f2tf32(v.y);
                s[2] = f2tf32(v.z); s[3] = f2tf32(v.w);
            }
        }
        {
            const float* gp = W + (size_t)(kt * 32 + brow) * C1 + bn0 + bcol;
#pragma unroll
            for (int q = 0; q < 4; q++) {
                float4 v = *(const float4*)(gp + q * 4);
                uint32_t* s = &sB[brow * SB_LD + bcol + q * 4];
                s[0] = f2tf32(v.x); s[1] = f2tf32(v.y);
                s[2] = f2tf32(v.z); s[3] = f2tf32(v.w);
            }
        }
        __syncthreads();

#pragma unroll
        for (int ks = 0; ks < 4; ks++) {
            const int kb = ks * 8;
            uint32_t af[4][4], bf[4][2];
#pragma unroll
            for (int mf = 0; mf < 4; mf++) {
                const uint32_t* ap = &sA[(warpM * 64 + mf * 16 + qid) * SA_LD + kb + tq];
                af[mf][0] = ap[0];
                af[mf][1] = ap[8 * SA_LD];
                af[mf][2] = ap[4];
                af[mf][3] = ap[8 * SA_LD + 4];
            }
#pragma unroll
            for (int nf = 0; nf < 4; nf++) {
                const uint32_t* bp = &sB[(kb + tq) * SB_LD + warpN * 32 + nf * 8 + qid];
                bf[nf][0] = bp[0];
                bf[nf][1] = bp[4 * SB_LD];
            }
#pragma unroll
            for (int mf = 0; mf < 4; mf++)
#pragma unroll
                for (int nf = 0; nf < 4; nf++)
                    mma_tf32(acc[mf][nf], af[mf], bf[nf]);
        }
        __syncthreads();
    }

#pragma unroll
    for (int mf = 0; mf < 4; mf++) {
        int m_base = bm0 + warpM * 64 + mf * 16;
        int r0 = m_base + qid, r1 = m_base + qid + 8;
        float s0 = 0.f, d0 = 0.f, s1 = 0.f, d1 = 0.f;
#pragma unroll
        for (int nf = 0; nf < 4; nf++) {
            int lc = warpN * 32 + nf * 8 + 2 * tq;
            float as0 = sAs[lc], as1 = sAs[lc + 1];
            float ad0 = sAd[lc], ad1 = sAd[lc + 1];
            s0 += acc[mf][nf][0] * as0 + acc[mf][nf][1] * as1;
            d0 += acc[mf][nf][0] * ad0 + acc[mf][nf][1] * ad1;
            s1 += acc[mf][nf][2] * as0 + acc[mf][nf][3] * as1;
            d1 += acc[mf][nf][2] * ad0 + acc[mf][nf][3] * ad1;
            if (r0 < M)
                *(float2*)&XW[(size_t)r0 * C1 + bn0 + lc] =
                    make_float2(acc[mf][nf][0], acc[mf][nf][1]);
            if (r1 < M)
                *(float2*)&XW[(size_t)r1 * C1 + bn0 + lc] =
                    make_float2(acc[mf][nf][2], acc[mf][nf][3]);
        }
#pragma unroll
        for (int o = 1; o < 4; o <<= 1) {
            s0 += __shfl_xor_sync(0xffffffffu, s0, o);
            d0 += __shfl_xor_sync(0xffffffffu, d0, o);
            s1 += __shfl_xor_sync(0xffffffffu, s1, o);
            d1 += __shfl_xor_sync(0xffffffffu, d1, o);
        }
        if (tq == 0) {
            if (r0 < M) { atomicAdd(&g_as[r0], s0); atomicAdd(&g_ad[r0], d0); }
            if (r1 < M) { atomicAdd(&g_as[r1], s1); atomicAdd(&g_ad[r1], d1); }
        }
    }
}

// ============================================================================
// GEMM2 (mma.sync tf32): out = relu(relu(agg+b) @ W2 + b2) @ Wo + bo
// ============================================================================
__global__ void __launch_bounds__(256, 2)
gat_gemm2(const float* __restrict__ A, const float* __restrict__ W2,
          const float* __restrict__ bin, const float* __restrict__ b2p,
          const float* __restrict__ Wo, const float* __restrict__ bo,
          float* __restrict__ out, int M)
{
    __shared__ uint32_t sA[128 * SA_LD];
    __shared__ uint32_t sB[32 * SB_LD];
    __shared__ float sBias[C1];
    __shared__ float sB2[C2];
    __shared__ float sWo[C2 * NOUT];
    __shared__ float sOut[128 * NOUT];

    const int tid   = threadIdx.x;
    const int lane  = tid & 31;
    const int wid   = tid >> 5;
    const int qid   = lane >> 2;
    const int tq    = lane & 3;
    const int warpM = wid & 1;
    const int warpN = wid >> 1;
    const int bm0   = blockIdx.y * 128;

    if (tid < C1) sBias[tid] = bin[tid];
    if (tid < C2) sB2[tid] = b2p[tid];
    for (int i = tid; i < C2 * NOUT; i += 256) sWo[i] = Wo[i];
    for (int i = tid; i < 128 * NOUT; i += 256) sOut[i] = 0.f;

    float acc[4][4][4];
#pragma unroll
    for (int i = 0; i < 4; i++)
#pragma unroll
        for (int j = 0; j < 4; j++)
#pragma unroll
            for (int q = 0; q < 4; q++) acc[i][j][q] = 0.f;

    const int arow = tid >> 1, acol = (tid & 1) * 16;
    const int brow = tid >> 3, bcol = (tid & 7) * 16;

    __syncthreads();

    for (int kt = 0; kt < C1 / 32; kt++) {
        {
            bool valid = (bm0 + arow) < M;
            const float* gp = A + (size_t)(bm0 + arow) * C1 + kt * 32 + acol;
#pragma unroll
            for (int q = 0; q < 4; q++) {
                int kb = kt * 32 + acol + q * 4;
                float4 v = valid ? *(const float4*)(gp + q * 4)
                                 : make_float4(0.f, 0.f, 0.f, 0.f);
                v.x = fmaxf(v.x + sBias[kb + 0], 0.f);
                v.y = fmaxf(v.y + sBias[kb + 1], 0.f);
                v.z = fmaxf(v.z + sBias[kb + 2], 0.f);
                v.w = fmaxf(v.w + sBias[kb + 3], 0.f);
                uint32_t* s = &sA[arow * SA_LD + acol + q * 4];
                s[0] = f2tf32(v.x); s[1] = f2tf32(v.y);
                s[2] = f2tf32(v.z); s[3] = f2tf32(v.w);
            }
        }
        {
            const float* gp = W2 + (size_t)(kt * 32 + brow) * C2 + bcol;
#pragma unroll
            for (int q = 0; q < 4; q++) {
                float4 v = *(const float4*)(gp + q * 4);
                uint32_t* s = &sB[brow * SB_LD + bcol + q * 4];
                s[0] = f2tf32(v.x); s[1] = f2tf32(v.y);
                s[2] = f2tf32(v.z); s[3] = f2tf32(v.w);
            }
        }
        __syncthreads();

#pragma unroll
        for (int ks = 0; ks < 4; ks++) {
            const int kb = ks * 8;
            uint32_t af[4][4], bf[4][2];
#pragma unroll
            for (int mf = 0; mf < 4; mf++) {
                const uint32_t* ap = &sA[(warpM * 64 + mf * 16 + qid) * SA_LD + kb + tq];
                af[mf][0] = ap[0];
                af[mf][1] = ap[8 * SA_LD];
                af[mf][2] = ap[4];
                af[mf][3] = ap[8 * SA_LD + 4];
            }
#pragma unroll
            for (int nf = 0; nf < 4; nf++) {
                const uint32_t* bp = &sB[(kb + tq) * SB_LD + warpN * 32 + nf * 8 + qid];
                bf[nf][0] = bp[0];
                bf[nf][1] = bp[4 * SB_LD];
            }
#pragma unroll
            for (int mf = 0; mf < 4; mf++)
#pragma unroll
                for (int nf = 0; nf < 4; nf++)
                    mma_tf32(acc[mf][nf], af[mf], bf[nf]);
        }
        __syncthreads();
    }

#pragma unroll
    for (int mf = 0; mf < 4; mf++) {
        int rl0 = warpM * 64 + mf * 16 + qid;
        int rl1 = rl0 + 8;
        float po0[NOUT], po1[NOUT];
#pragma unroll
        for (int o = 0; o < NOUT; o++) { po0[o] = 0.f; po1[o] = 0.f; }
#pragma unroll
        for (int nf = 0; nf < 4; nf++) {
            int lc = warpN * 32 + nf * 8 + 2 * tq;
            float h00 = fmaxf(acc[mf][nf][0] + sB2[lc],     0.f);
            float h01 = fmaxf(acc[mf][nf][1] + sB2[lc + 1], 0.f);
            float h10 = fmaxf(acc[mf][nf][2] + sB2[lc],     0.f);
            float h11 = fmaxf(acc[mf][nf][3] + sB2[lc + 1], 0.f);
#pragma unroll
            for (int o = 0; o < NOUT; o++) {
                po0[o] += h00 * sWo[lc * NOUT + o] + h01 * sWo[(lc + 1) * NOUT + o];
                po1[o] += h10 * sWo[lc * NOUT + o] + h11 * sWo[(lc + 1) * NOUT + o];
            }
        }
#pragma unroll
        for (int o = 0; o < NOUT; o++) {
#pragma unroll
            for (int sft = 1; sft < 4; sft <<= 1) {
                po0[o] += __shfl_xor_sync(0xffffffffu, po0[o], sft);
                po1[o] += __shfl_xor_sync(0xffffffffu, po1[o], sft);
            }
        }
        if (tq == 0) {
#pragma unroll
            for (int o = 0; o < NOUT; o++) {
                atomicAdd(&sOut[rl0 * NOUT + o], po0[o]);
                atomicAdd(&sOut[rl1 * NOUT + o], po1[o]);
            }
        }
    }
    __syncthreads();
    for (int i = tid; i < 128 * NOUT; i += 256) {
        int rl = i / NOUT, o = i % NOUT;
        int row = bm0 + rl;
        if (row < M) out[(size_t)row * NOUT + o] = sOut[i] + bo[o];
    }
}

// ---------------- degree histogram (only needs dst indices) -----------------
__global__ void deg_hist(const int* __restrict__ ei, int E, int n)
{
    int i = blockIdx.x * blockDim.x + threadIdx.x;
    if (i >= E + n) return;
    int d = (i < E) ? __ldg(&ei[E + i]) : (i - E);
    atomicAdd(&g_deg[d], 1);
}

// ---------------- CSR scan (3 small kernels) --------------------------------
#define SCB 512
__global__ void scan1(int n)
{
    __shared__ int s[SCB];
    int tid = threadIdx.x;
    int i = blockIdx.x * SCB + tid;
    int v = (i < n) ? g_deg[i] : 0;
    s[tid] = v; __syncthreads();
#pragma unroll
    for (int off = 1; off < SCB; off <<= 1) {
        int t = (tid >= off) ? s[tid - off] : 0;
        __syncthreads();
        s[tid] += t;
        __syncthreads();
    }
    if (i < n) g_rowptr[i] = s[tid] - v;
    if (tid == SCB - 1) g_bsum[blockIdx.x] = s[tid];
}
__global__ void scan2(int nb)
{
    __shared__ int s[256];
    int tid = threadIdx.x;
    int v = (tid < nb) ? g_bsum[tid] : 0;
    s[tid] = v; __syncthreads();
#pragma unroll
    for (int off = 1; off < 256; off <<= 1) {
        int t = (tid >= off) ? s[tid - off] : 0;
        __syncthreads();
        s[tid] += t;
        __syncthreads();
    }
    if (tid < nb) g_bsum[tid] = s[tid] - v;
}
__global__ void scan3(int n)
{
    int i = blockIdx.x * blockDim.x + threadIdx.x;
    if (i >= n) return;
    int r = g_rowptr[i] + g_bsum[i / SCB];
    g_rowptr[i] = r;
    g_cur[i] = r;
}

// ---------------- fill CSR buckets (src only; weight computed later) --------
__global__ void fill_csr(const int* __restrict__ ei, int E, int n)
{
    int i = blockIdx.x * blockDim.x + threadIdx.x;
    if (i >= E + n) return;
    int s, d;
    if (i < E) { s = __ldg(&ei[i]); d = __ldg(&ei[E + i]); } else { s = d = i - E; }
    int pos = atomicAdd(&g_cur[d], 1);
    g_csr[pos] = s;
}

// ---------------- aggregate: warp per dst; softmax normalized in-place ------
__global__ void aggregate(int n)
{
    int warp = (int)(((size_t)blockIdx.x * blockDim.x + threadIdx.x) >> 5);
    int lane = threadIdx.x & 31;
    if (warp >= n) return;
    int start = g_rowptr[warp];
    int deg   = g_deg[warp];
    float add = g_ad[warp];
    const float4* xw4 = (const float4*)g_xw;
    float4 a0 = make_float4(0.f, 0.f, 0.f, 0.f);
    float4 a1 = make_float4(0.f, 0.f, 0.f, 0.f);
    float wsum = 0.f;
    for (int c = 0; c < deg; c += 32) {
        int idx = c + lane;
        int src = 0; float w = 0.f;
        if (idx < deg) {
            src = __ldg(&g_csr[start + idx]);
            float e = g_as[src] + add;
            e = e > 0.f ? e : 0.2f * e;      // LeakyReLU(0.2)
            w = __expf(e);
            wsum += w;
        }
        int cnt = min(32, deg - c);
        for (int k = 0; k < cnt; k++) {
            int   s  = __shfl_sync(0xffffffffu, src, k);
            float ww = __shfl_sync(0xffffffffu, w, k);
            const float4* sp = &xw4[(size_t)s * 64];
            float4 v0 = __ldg(&sp[lane]);
            float4 v1 = __ldg(&sp[lane + 32]);
            a0.x += ww * v0.x; a0.y += ww * v0.y; a0.z += ww * v0.z; a0.w += ww * v0.w;
            a1.x += ww * v1.x; a1.y += ww * v1.y; a1.z += ww * v1.z; a1.w += ww * v1.w;
        }
    }
#pragma unroll
    for (int o = 16; o > 0; o >>= 1)
        wsum += __shfl_xor_sync(0xffffffffu, wsum, o);
    float inv = __frcp_rn(wsum);
    float4* dst = (float4*)&g_agg[(size_t)warp * C1];
    a0.x *= inv; a0.y *= inv; a0.z *= inv; a0.w *= inv;
    a1.x *= inv; a1.y *= inv; a1.z *= inv; a1.w *= inv;
    dst[lane]      = a0;
    dst[lane + 32] = a1;
}

// ---------------- launch ----------------------------------------------------
extern "C" void kernel_launch(void* const* d_in, const int* in_sizes, int n_in,
                              void* d_out, int out_size)
{
    const float* x     = (const float*)d_in[0];
    const int*   ei    = (const int*)  d_in[1];
    const float* W     = (const float*)d_in[2];
    const float* a_src = (const float*)d_in[3];
    const float* a_dst = (const float*)d_in[4];
    const float* b     = (const float*)d_in[5];
    const float* W2    = (const float*)d_in[6];
    const float* b2    = (const float*)d_in[7];
    const float* Wo    = (const float*)d_in[8];
    const float* bo    = (const float*)d_in[9];

    const int n = in_sizes[0] / F0;   // 100000
    const int E = in_sizes[1] / 2;    // 800000
    const int tot = E + n;
    const int nb = (n + SCB - 1) / SCB;

    float *xw, *agg, *as_, *ad_;
    int *deg;
    cudaGetSymbolAddress((void**)&xw,  g_xw);
    cudaGetSymbolAddress((void**)&agg, g_agg);
    cudaGetSymbolAddress((void**)&as_, g_as);
    cudaGetSymbolAddress((void**)&ad_, g_ad);
    cudaGetSymbolAddress((void**)&deg, g_deg);

    cudaMemsetAsync(as_, 0, (size_t)n * sizeof(float));
    cudaMemsetAsync(ad_, 0, (size_t)n * sizeof(float));
    cudaMemsetAsync(deg, 0, (size_t)n * sizeof(int));

    // CSR build (independent of GEMM1)
    deg_hist<<<(tot + 255) / 256, 256>>>(ei, E, n);
    scan1<<<nb, SCB>>>(n);
    scan2<<<1, 256>>>(nb);
    scan3<<<(n + 255) / 256, 256>>>(n);
    fill_csr<<<(tot + 255) / 256, 256>>>(ei, E, n);
    // GEMM1 + fused alpha
    {
        dim3 grid(C1 / 128, (n + 127) / 128);
        gat_gemm1<<<grid, 256>>>(x, W, a_src, a_dst, xw, n);
    }
    // aggregate (warp per dst; computes weights + normalization internally)
    {
        size_t threads = (size_t)n * 32;
        aggregate<<<(unsigned)((threads + 255) / 256), 256>>>(n);
    }
    // GEMM2 + fused output projection
    {
        dim3 grid(1, (n + 127) / 128);
        gat_gemm2<<<grid, 256>>>(agg, W2, b, b2, Wo, bo, (float*)d_out, n);
    }
}